// round 12
// baseline (speedup 1.0000x reference)
#include <cuda_runtime.h>
#include <math.h>

#define C_ 64
#define NSEG_ 100000
#define NMAX_ 1000000

typedef unsigned long long ull;

// ---- scratch (device globals; no allocation allowed) ----
__device__ __align__(16) float  g_y[(size_t)NMAX_ * C_];   // pre-BN pre_mix (y)
__device__ __align__(16) float  g_q[NSEG_ * C_];           // -feat_add/(tmp_w+eps)
__device__ __align__(16) double g_stats[4 * C_];           // sum1|sq1|sum2|sq2 (fp64)
__device__ __align__(16) float  g_aff[4 * C_];             // a1|c1|a2|c2
__device__ int g_cnt[NSEG_];                               // per-segment row count
__device__ int g_base[NSEG_];                              // exclusive prefix of cnt
__device__ int g_cur[NSEG_];                               // scatter cursors
__device__ int g_list[NMAX_];                              // rows grouped by segment

// ---- packed f32x2 helpers (Blackwell FFMA2 path) ----
static __device__ __forceinline__ float2 f2fma(float2 a, float2 b, float2 c) {
    float2 d;
    asm("fma.rn.f32x2 %0, %1, %2, %3;"
        : "=l"(reinterpret_cast<ull&>(d))
        : "l"(reinterpret_cast<ull&>(a)),
          "l"(reinterpret_cast<ull&>(b)),
          "l"(reinterpret_cast<ull&>(c)));
    return d;
}
static __device__ __forceinline__ float2 f2add(float2 a, float2 b) {
    float2 d;
    asm("add.rn.f32x2 %0, %1, %2;"
        : "=l"(reinterpret_cast<ull&>(d))
        : "l"(reinterpret_cast<ull&>(a)), "l"(reinterpret_cast<ull&>(b)));
    return d;
}
static __device__ __forceinline__ float2 f2mul(float2 a, float2 b) {
    float2 d;
    asm("mul.rn.f32x2 %0, %1, %2;"
        : "=l"(reinterpret_cast<ull&>(d))
        : "l"(reinterpret_cast<ull&>(a)), "l"(reinterpret_cast<ull&>(b)));
    return d;
}
static __device__ __forceinline__ float2 f2dup(float x) {
    float2 d;
    asm("mov.b64 %0, {%1, %1};" : "=l"(reinterpret_cast<ull&>(d)) : "f"(x));
    return d;
}

// pos_w for 2 channels: fma-chain in K order, bias added last
static __device__ __forceinline__ float2 posw2(float2 X, float2 Y, float2 Z,
                                               float2 w0, float2 w1, float2 w2,
                                               float2 b) {
    return f2add(f2fma(Z, w2, f2fma(Y, w1, f2mul(X, w0))), b);
}

// warp reduce over lanes with equal (lane & 3)
static __device__ __forceinline__ void warp_reduce_g(float2 ssum[8], float2 ssq[8]) {
#pragma unroll
    for (int j = 0; j < 8; j++) {
#pragma unroll
        for (int m = 4; m < 32; m <<= 1) {
            ssum[j].x += __shfl_xor_sync(0xffffffffu, ssum[j].x, m);
            ssum[j].y += __shfl_xor_sync(0xffffffffu, ssum[j].y, m);
            ssq[j].x  += __shfl_xor_sync(0xffffffffu, ssq[j].x, m);
            ssq[j].y  += __shfl_xor_sync(0xffffffffu, ssq[j].y, m);
        }
    }
}

// block-level fp64 stats flush. sStat layout: [0:64)=sum, [64:128)=sq.
static __device__ __forceinline__ void block_stats_flush(
    int t, int g, const float2 ssum[8], const float2 ssq[8],
    double* sStat, double* gdst)
{
    if ((t & 31) < 4) {
#pragma unroll
        for (int j = 0; j < 8; j++) {
            int c = g * 16 + 2 * j;
            atomicAdd(&sStat[c],          (double)ssum[j].x);
            atomicAdd(&sStat[c + 1],      (double)ssum[j].y);
            atomicAdd(&sStat[64 + c],     (double)ssq[j].x);
            atomicAdd(&sStat[64 + c + 1], (double)ssq[j].y);
        }
    }
    __syncthreads();
    if (t < 128) atomicAdd(&gdst[t], sStat[t]);
}

// --------------------------------------------------------------------------
// Pass 1: y = feat@W_pre + b_pre (stored) + BN1 stats. Pure GEMM now.
// --------------------------------------------------------------------------
__global__ __launch_bounds__(256, 2) void k_pass1(
    const float* __restrict__ feat,
    const float* __restrict__ Wpre, const float* __restrict__ bpre, int N)
{
    __shared__ float sW[C_ * C_];
    __shared__ float sb1[C_];
    __shared__ double sStat[128];
    int t = threadIdx.x;
    {
        float4* d = (float4*)sW;
        const float4* s = (const float4*)Wpre;
#pragma unroll
        for (int i = 0; i < 4; i++) d[t + 256 * i] = s[t + 256 * i];
        if (t < 16) ((float4*)sb1)[t] = ((const float4*)bpre)[t];
        if (t < 128) sStat[t] = 0.0;
    }
    __syncthreads();

    const int g = t & 3;   // channels [16g, 16g+16)
    const float2* sb1p = (const float2*)sb1 + g * 8;

    float2 ssum[8], ssq[8];
#pragma unroll
    for (int j = 0; j < 8; j++) { ssum[j] = make_float2(0.f, 0.f); ssq[j] = make_float2(0.f, 0.f); }

    const int tid = blockIdx.x * 256 + t;
    const int rstep = gridDim.x * 128;         // 128 rows per block-iteration
    for (int r0 = (tid >> 2) * 2; r0 < N; r0 += rstep) {
        const int r1 = r0 + 1;
        const bool v1 = (r1 < N);
        float2 acc0[8], acc1[8];
#pragma unroll
        for (int j = 0; j < 8; j++) { acc0[j] = sb1p[j]; acc1[j] = acc0[j]; }

        const float4* a0p = (const float4*)(feat + (size_t)r0 * C_);
        const float4* a1p = (const float4*)(feat + (size_t)r1 * C_);
#pragma unroll 4
        for (int kc = 0; kc < 16; kc++) {
            float4 av0 = __ldg(a0p + kc);
            float4 av1 = v1 ? __ldg(a1p + kc) : make_float4(0.f, 0.f, 0.f, 0.f);
#pragma unroll
            for (int u = 0; u < 4; u++) {
                float2 A0 = f2dup(((const float*)&av0)[u]);
                float2 A1 = f2dup(((const float*)&av1)[u]);
                const float4* wr = (const float4*)(sW + (kc * 4 + u) * C_ + g * 16);
#pragma unroll
                for (int j2 = 0; j2 < 4; j2++) {
                    float4 w = wr[j2];
                    float2 wl = make_float2(w.x, w.y);
                    float2 wh = make_float2(w.z, w.w);
                    acc0[2 * j2]     = f2fma(A0, wl, acc0[2 * j2]);
                    acc0[2 * j2 + 1] = f2fma(A0, wh, acc0[2 * j2 + 1]);
                    acc1[2 * j2]     = f2fma(A1, wl, acc1[2 * j2]);
                    acc1[2 * j2 + 1] = f2fma(A1, wh, acc1[2 * j2 + 1]);
                }
            }
        }
        // epilogue: stats + store y
#pragma unroll
        for (int j = 0; j < 8; j++) {
            ssum[j] = f2add(ssum[j], acc0[j]);
            ssq[j]  = f2fma(acc0[j], acc0[j], ssq[j]);
        }
        float4* yo0 = (float4*)(g_y + (size_t)r0 * C_ + g * 16);
#pragma unroll
        for (int j2 = 0; j2 < 4; j2++) {
            float4 o;
            o.x = acc0[2 * j2].x;     o.y = acc0[2 * j2].y;
            o.z = acc0[2 * j2 + 1].x; o.w = acc0[2 * j2 + 1].y;
            yo0[j2] = o;
        }
        if (v1) {
#pragma unroll
            for (int j = 0; j < 8; j++) {
                ssum[j] = f2add(ssum[j], acc1[j]);
                ssq[j]  = f2fma(acc1[j], acc1[j], ssq[j]);
            }
            float4* yo1 = (float4*)(g_y + (size_t)r1 * C_ + g * 16);
#pragma unroll
            for (int j2 = 0; j2 < 4; j2++) {
                float4 o;
                o.x = acc1[2 * j2].x;     o.y = acc1[2 * j2].y;
                o.z = acc1[2 * j2 + 1].x; o.w = acc1[2 * j2 + 1].y;
                yo1[j2] = o;
            }
        }
    }

    warp_reduce_g(ssum, ssq);
    block_stats_flush(t, g, ssum, ssq, sStat, g_stats);
}

// --------------------------------------------------------------------------
// Segment-list construction: histogram -> scan -> scatter -> per-segment sort
// --------------------------------------------------------------------------
__global__ __launch_bounds__(256) void k_hist(const int* __restrict__ inv, int N)
{
    for (int r = blockIdx.x * 256 + threadIdx.x; r < N; r += gridDim.x * 256)
        atomicAdd(&g_cnt[__ldg(inv + r)], 1);
}

__global__ __launch_bounds__(1024) void k_scan()
{
    __shared__ int ssum[1024];
    int t = threadIdx.x;
    const int per = (NSEG_ + 1023) / 1024;   // 98
    int lo = t * per, hi = min(lo + per, NSEG_);
    int loc = 0;
    for (int s = lo; s < hi; s++) loc += g_cnt[s];
    ssum[t] = loc;
    __syncthreads();
    for (int off = 1; off < 1024; off <<= 1) {
        int v = (t >= off) ? ssum[t - off] : 0;
        __syncthreads();
        ssum[t] += v;
        __syncthreads();
    }
    int run = (t == 0) ? 0 : ssum[t - 1];
    for (int s = lo; s < hi; s++) { g_base[s] = run; run += g_cnt[s]; }
}

__global__ __launch_bounds__(256) void k_scatter(const int* __restrict__ inv, int N)
{
    for (int r = blockIdx.x * 256 + threadIdx.x; r < N; r += gridDim.x * 256) {
        int s = __ldg(inv + r);
        int p = atomicAdd(&g_cur[s], 1);
        g_list[g_base[s] + p] = r;
    }
}

__global__ __launch_bounds__(256) void k_sortseg()
{
    int s = blockIdx.x * 256 + threadIdx.x;
    if (s >= NSEG_) return;
    int b = g_base[s], n = g_cnt[s];
    for (int i = 1; i < n; i++) {
        int key = g_list[b + i];
        int j = i - 1;
        while (j >= 0 && g_list[b + j] > key) {
            g_list[b + j + 1] = g_list[b + j];
            j--;
        }
        g_list[b + j + 1] = key;
    }
}

// --------------------------------------------------------------------------
// BN affine: a = gamma*rsqrt(var+1e-3), c = beta - mean*a.  which=0 -> BN1.
// --------------------------------------------------------------------------
__global__ void k_aff(const float* __restrict__ gam, const float* __restrict__ bet,
                      int which, double invN)
{
    int c = threadIdx.x;
    if (c < C_) {
        double m = g_stats[which * 128 + c] * invN;
        double v = g_stats[which * 128 + 64 + c] * invN - m * m;
        double a = (double)__ldg(gam + c) * rsqrt(v + 1e-3);
        g_aff[which * 128 + c] = (float)a;
        g_aff[which * 128 + 64 + c] = (float)((double)__ldg(bet + c) - m * a);
    }
}

// --------------------------------------------------------------------------
// k_seg: one warp per segment; lane handles channels (l, l+32).
// Sequential fp32 accumulation in increasing row order — bit-matches a
// deterministic row-ordered reference segment_sum. Product rounded before
// add (no fma) to match elementwise tmp = pos_w*feat then sum.
// Emits q = -S_py / (S_p + 1e-4) directly.
// --------------------------------------------------------------------------
__global__ __launch_bounds__(256) void k_seg(
    const float* __restrict__ xyz,
    const float* __restrict__ Wpos, const float* __restrict__ bpos)
{
    int w = (blockIdx.x * 256 + threadIdx.x) >> 5;
    int l = threadIdx.x & 31;
    if (w >= NSEG_) return;

    float P0a = __ldg(Wpos + l),        P0b = __ldg(Wpos + 32 + l);
    float P1a = __ldg(Wpos + 64 + l),   P1b = __ldg(Wpos + 96 + l);
    float P2a = __ldg(Wpos + 128 + l),  P2b = __ldg(Wpos + 160 + l);
    float Ba  = __ldg(bpos + l),        Bb  = __ldg(bpos + 32 + l);
    float a1a = g_aff[l],       a1b = g_aff[32 + l];
    float c1a = g_aff[64 + l],  c1b = g_aff[96 + l];

    int b = g_base[w], n = g_cnt[w];
    float sp0 = 0.f, sp1 = 0.f, sy0 = 0.f, sy1 = 0.f;
    for (int i = 0; i < n; i++) {
        int r = g_list[b + i];
        float fx = floorf(__ldg(xyz + 3 * r));
        float fy = floorf(__ldg(xyz + 3 * r + 1));
        float fz = floorf(__ldg(xyz + 3 * r + 2));
        float pwa = __fadd_rn(fmaf(fz, P2a, fmaf(fy, P1a, __fmul_rn(fx, P0a))), Ba);
        float pwb = __fadd_rn(fmaf(fz, P2b, fmaf(fy, P1b, __fmul_rn(fx, P0b))), Bb);
        float ya = __ldg(g_y + (size_t)r * C_ + l);
        float yb = __ldg(g_y + (size_t)r * C_ + 32 + l);
        float fa = fmaf(a1a, ya, c1a);
        float fb = fmaf(a1b, yb, c1b);
        sp0 = __fadd_rn(sp0, pwa);
        sp1 = __fadd_rn(sp1, pwb);
        sy0 = __fadd_rn(sy0, __fmul_rn(pwa, fa));
        sy1 = __fadd_rn(sy1, __fmul_rn(pwb, fb));
    }
    g_q[(size_t)w * C_ + l]      = __fdiv_rn(-sy0, __fadd_rn(sp0, 1e-4f));
    g_q[(size_t)w * C_ + 32 + l] = __fdiv_rn(-sy1, __fadd_rn(sp1, 1e-4f));
}

// --------------------------------------------------------------------------
// Pass 2: BN2 stats over out_pre = pos_w * q[seg]   (pos_w recomputed)
// --------------------------------------------------------------------------
__global__ __launch_bounds__(256, 2) void k_pass2(
    const float* __restrict__ xyz, const int* __restrict__ inv,
    const float* __restrict__ Wpos, const float* __restrict__ bpos, int N)
{
    __shared__ float sP[3 * C_];
    __shared__ float sb2[C_];
    __shared__ double sStat[128];
    int t = threadIdx.x;
    if (t < 48) ((float4*)sP)[t] = ((const float4*)Wpos)[t];
    if (t >= 64 && t < 80) ((float4*)sb2)[t - 64] = ((const float4*)bpos)[t - 64];
    if (t < 128) sStat[t] = 0.0;
    __syncthreads();

    const int g = t & 3;
    const float2* P0 = (const float2*)sP + g * 8;
    const float2* P1 = (const float2*)(sP + 64) + g * 8;
    const float2* P2 = (const float2*)(sP + 128) + g * 8;
    const float2* sbp = (const float2*)sb2 + g * 8;

    float2 ssum[8], ssq[8];
#pragma unroll
    for (int j = 0; j < 8; j++) { ssum[j] = make_float2(0.f, 0.f); ssq[j] = make_float2(0.f, 0.f); }

    const int tid = blockIdx.x * 256 + t;
    const int rstep = gridDim.x * 64;
    for (int r = tid >> 2; r < N; r += rstep) {
        float fx = floorf(__ldg(xyz + (size_t)r * 3 + 0));
        float fy = floorf(__ldg(xyz + (size_t)r * 3 + 1));
        float fz = floorf(__ldg(xyz + (size_t)r * 3 + 2));
        float2 X = f2dup(fx), Y = f2dup(fy), Z = f2dup(fz);
        int s = __ldg(inv + r);
        const float4* qr = (const float4*)(g_q + (size_t)s * C_ + g * 16);
#pragma unroll
        for (int j2 = 0; j2 < 4; j2++) {
            float4 qv = __ldg(qr + j2);
            float2 pl = posw2(X, Y, Z, P0[2 * j2], P1[2 * j2], P2[2 * j2], sbp[2 * j2]);
            float2 ph = posw2(X, Y, Z, P0[2 * j2 + 1], P1[2 * j2 + 1], P2[2 * j2 + 1],
                              sbp[2 * j2 + 1]);
            float2 ol = f2mul(pl, make_float2(qv.x, qv.y));
            float2 oh = f2mul(ph, make_float2(qv.z, qv.w));
            ssum[2 * j2]     = f2add(ssum[2 * j2], ol);
            ssq[2 * j2]      = f2fma(ol, ol, ssq[2 * j2]);
            ssum[2 * j2 + 1] = f2add(ssum[2 * j2 + 1], oh);
            ssq[2 * j2 + 1]  = f2fma(oh, oh, ssq[2 * j2 + 1]);
        }
    }

    warp_reduce_g(ssum, ssq);
    block_stats_flush(t, g, ssum, ssq, sStat, g_stats + 128);
}

// --------------------------------------------------------------------------
// Final: out = relu(a2*(pos_w*q[seg]) + c2) + (a1*y + c1)
// --------------------------------------------------------------------------
__global__ __launch_bounds__(256, 2) void k_final(
    const float* __restrict__ xyz, const int* __restrict__ inv,
    const float* __restrict__ Wpos, const float* __restrict__ bpos,
    float* __restrict__ out, int N)
{
    __shared__ float sP[3 * C_];
    __shared__ float sb2[C_];
    __shared__ float saff[4 * C_];
    int t = threadIdx.x;
    if (t < 48) ((float4*)sP)[t] = ((const float4*)Wpos)[t];
    if (t >= 64 && t < 80) ((float4*)sb2)[t - 64] = ((const float4*)bpos)[t - 64];
    if (t >= 128 && t < 192) ((float4*)saff)[t - 128] = ((const float4*)g_aff)[t - 128];
    __syncthreads();

    const int g = t & 3;
    const float2* P0 = (const float2*)sP + g * 8;
    const float2* P1 = (const float2*)(sP + 64) + g * 8;
    const float2* P2 = (const float2*)(sP + 128) + g * 8;
    const float2* sbp = (const float2*)sb2 + g * 8;
    const float2* A1 = (const float2*)saff + g * 8;
    const float2* C1 = (const float2*)(saff + 64) + g * 8;
    const float2* A2 = (const float2*)(saff + 128) + g * 8;
    const float2* C2 = (const float2*)(saff + 192) + g * 8;

    const int tid = blockIdx.x * 256 + t;
    const int rstep = gridDim.x * 64;
    for (int r = tid >> 2; r < N; r += rstep) {
        float fx = floorf(__ldg(xyz + (size_t)r * 3 + 0));
        float fy = floorf(__ldg(xyz + (size_t)r * 3 + 1));
        float fz = floorf(__ldg(xyz + (size_t)r * 3 + 2));
        float2 X = f2dup(fx), Y = f2dup(fy), Z = f2dup(fz);
        int s = __ldg(inv + r);
        const float4* qr = (const float4*)(g_q + (size_t)s * C_ + g * 16);
        const float4* yr = (const float4*)(g_y + (size_t)r * C_ + g * 16);
        float4* orow = (float4*)(out + (size_t)r * C_ + g * 16);
#pragma unroll
        for (int j2 = 0; j2 < 4; j2++) {
            float4 qv = __ldg(qr + j2);
            float4 yv = yr[j2];
            float2 pl = posw2(X, Y, Z, P0[2 * j2], P1[2 * j2], P2[2 * j2], sbp[2 * j2]);
            float2 ph = posw2(X, Y, Z, P0[2 * j2 + 1], P1[2 * j2 + 1], P2[2 * j2 + 1],
                              sbp[2 * j2 + 1]);
            float2 featl = f2fma(A1[2 * j2],     make_float2(yv.x, yv.y), C1[2 * j2]);
            float2 feath = f2fma(A1[2 * j2 + 1], make_float2(yv.z, yv.w), C1[2 * j2 + 1]);
            float2 opl = f2mul(pl, make_float2(qv.x, qv.y));
            float2 oph = f2mul(ph, make_float2(qv.z, qv.w));
            float2 bnl = f2fma(A2[2 * j2],     opl, C2[2 * j2]);
            float2 bnh = f2fma(A2[2 * j2 + 1], oph, C2[2 * j2 + 1]);
            float4 o;
            o.x = fmaxf(bnl.x, 0.f) + featl.x;
            o.y = fmaxf(bnl.y, 0.f) + featl.y;
            o.z = fmaxf(bnh.x, 0.f) + feath.x;
            o.w = fmaxf(bnh.y, 0.f) + feath.y;
            orow[j2] = o;
        }
    }
}

// --------------------------------------------------------------------------
extern "C" void kernel_launch(void* const* d_in, const int* in_sizes, int n_in,
                              void* d_out, int out_size)
{
    const float* xyz  = (const float*)d_in[0];
    const float* feat = (const float*)d_in[1];
    const int*   inv  = (const int*)d_in[2];
    const float* Wpre = (const float*)d_in[3];
    const float* bpre = (const float*)d_in[4];
    const float* g1   = (const float*)d_in[5];
    const float* be1  = (const float*)d_in[6];
    const float* Wpos = (const float*)d_in[7];
    const float* bpos = (const float*)d_in[8];
    const float* g2   = (const float*)d_in[9];
    const float* be2  = (const float*)d_in[10];
    float* out = (float*)d_out;
    const int N = in_sizes[1] / C_;

    void *pCnt = nullptr, *pCur = nullptr, *pStats = nullptr;
    cudaGetSymbolAddress(&pCnt, g_cnt);
    cudaGetSymbolAddress(&pCur, g_cur);
    cudaGetSymbolAddress(&pStats, g_stats);

    cudaMemsetAsync(pCnt, 0, sizeof(int) * NSEG_, 0);
    cudaMemsetAsync(pCur, 0, sizeof(int) * NSEG_, 0);
    cudaMemsetAsync(pStats, 0, sizeof(double) * 4 * C_, 0);

    const int grid = 1184;
    const double invN = 1.0 / (double)N;

    // segment list construction (independent of GEMM results)
    k_hist<<<grid, 256>>>(inv, N);
    k_scan<<<1, 1024>>>();
    k_scatter<<<grid, 256>>>(inv, N);
    k_sortseg<<<(NSEG_ + 255) / 256, 256>>>();

    // GEMM + BN1 stats
    k_pass1<<<grid, 256>>>(feat, Wpre, bpre, N);
    k_aff<<<1, 64>>>(g1, be1, 0, invN);

    // sequential per-segment sums -> q
    k_seg<<<(NSEG_ * 32 + 255) / 256, 256>>>(xyz, Wpos, bpos);

    // BN2 stats + final
    k_pass2<<<grid, 256>>>(xyz, inv, Wpos, bpos, N);
    k_aff<<<1, 64>>>(g2, be2, 1, invN);
    k_final<<<grid, 256>>>(xyz, inv, Wpos, bpos, out, N);
}

// round 13
// speedup vs baseline: 1.4253x; 1.4253x over previous
#include <cuda_runtime.h>
#include <math.h>

#define C_ 64
#define NSEG_ 100000
#define NMAX_ 1000000

typedef unsigned long long ull;

// ---- scratch (device globals; no allocation allowed) ----
__device__ __align__(16) float  g_y[(size_t)NMAX_ * C_];   // pre-BN pre_mix (y)
__device__ __align__(16) float  g_q[NSEG_ * C_];           // -feat_add/(tmp_w+eps)
__device__ __align__(16) double g_stats[4 * C_];           // sum1|sq1|sum2|sq2 (fp64)
__device__ __align__(16) float  g_aff[4 * C_];             // a1|c1|a2|c2
__device__ int g_cnt[NSEG_];                               // per-segment row count
__device__ int g_base[NSEG_];                              // exclusive prefix of cnt
__device__ int g_cur[NSEG_];                               // scatter cursors
__device__ int g_list[NMAX_];                              // rows grouped by segment

// ---- packed f32x2 helpers (Blackwell FFMA2 path) ----
static __device__ __forceinline__ float2 f2fma(float2 a, float2 b, float2 c) {
    float2 d;
    asm("fma.rn.f32x2 %0, %1, %2, %3;"
        : "=l"(reinterpret_cast<ull&>(d))
        : "l"(reinterpret_cast<ull&>(a)),
          "l"(reinterpret_cast<ull&>(b)),
          "l"(reinterpret_cast<ull&>(c)));
    return d;
}
static __device__ __forceinline__ float2 f2add(float2 a, float2 b) {
    float2 d;
    asm("add.rn.f32x2 %0, %1, %2;"
        : "=l"(reinterpret_cast<ull&>(d))
        : "l"(reinterpret_cast<ull&>(a)), "l"(reinterpret_cast<ull&>(b)));
    return d;
}
static __device__ __forceinline__ float2 f2mul(float2 a, float2 b) {
    float2 d;
    asm("mul.rn.f32x2 %0, %1, %2;"
        : "=l"(reinterpret_cast<ull&>(d))
        : "l"(reinterpret_cast<ull&>(a)), "l"(reinterpret_cast<ull&>(b)));
    return d;
}
static __device__ __forceinline__ float2 f2dup(float x) {
    float2 d;
    asm("mov.b64 %0, {%1, %1};" : "=l"(reinterpret_cast<ull&>(d)) : "f"(x));
    return d;
}

// pos_w for 2 channels: fma-chain in K order, bias added last
static __device__ __forceinline__ float2 posw2(float2 X, float2 Y, float2 Z,
                                               float2 w0, float2 w1, float2 w2,
                                               float2 b) {
    return f2add(f2fma(Z, w2, f2fma(Y, w1, f2mul(X, w0))), b);
}

// warp reduce over lanes with equal (lane & 3)
static __device__ __forceinline__ void warp_reduce_g(float2 ssum[8], float2 ssq[8]) {
#pragma unroll
    for (int j = 0; j < 8; j++) {
#pragma unroll
        for (int m = 4; m < 32; m <<= 1) {
            ssum[j].x += __shfl_xor_sync(0xffffffffu, ssum[j].x, m);
            ssum[j].y += __shfl_xor_sync(0xffffffffu, ssum[j].y, m);
            ssq[j].x  += __shfl_xor_sync(0xffffffffu, ssq[j].x, m);
            ssq[j].y  += __shfl_xor_sync(0xffffffffu, ssq[j].y, m);
        }
    }
}

// block-level fp64 stats flush. sStat layout: [0:64)=sum, [64:128)=sq.
static __device__ __forceinline__ void block_stats_flush(
    int t, int g, const float2 ssum[8], const float2 ssq[8],
    double* sStat, double* gdst)
{
    if ((t & 31) < 4) {
#pragma unroll
        for (int j = 0; j < 8; j++) {
            int c = g * 16 + 2 * j;
            atomicAdd(&sStat[c],          (double)ssum[j].x);
            atomicAdd(&sStat[c + 1],      (double)ssum[j].y);
            atomicAdd(&sStat[64 + c],     (double)ssq[j].x);
            atomicAdd(&sStat[64 + c + 1], (double)ssq[j].y);
        }
    }
    __syncthreads();
    if (t < 128) atomicAdd(&gdst[t], sStat[t]);
}

// --------------------------------------------------------------------------
// Pass 1: y = feat@W_pre + b_pre (stored) + BN1 stats.
// W in smem with padded layout [k][4 groups][20 floats] -> conflict-free
// LDS.128 (banks {0,20,8,28} across the 4 channel-groups of a warp).
// --------------------------------------------------------------------------
#define WROW_ 80   // floats per k-row in padded layout (4 groups * 20)

__global__ __launch_bounds__(256, 2) void k_pass1(
    const float* __restrict__ feat,
    const float* __restrict__ Wpre, const float* __restrict__ bpre, int N)
{
    __shared__ float sW[C_ * WROW_];    // 20 KB
    __shared__ float sb1[C_];
    __shared__ double sStat[128];
    int t = threadIdx.x;
    {
        // scatter Wpre[k][c] -> sW[k*80 + (c/16)*20 + (c%16)]
#pragma unroll
        for (int i = 0; i < 16; i++) {
            int idx = t + 256 * i;          // 4096 elements
            int k = idx >> 6, c = idx & 63;
            sW[k * WROW_ + (c >> 4) * 20 + (c & 15)] = Wpre[idx];
        }
        if (t < 16) ((float4*)sb1)[t] = ((const float4*)bpre)[t];
        if (t < 128) sStat[t] = 0.0;
    }
    __syncthreads();

    const int g = t & 3;   // channels [16g, 16g+16)
    const float2* sb1p = (const float2*)sb1 + g * 8;

    float2 ssum[8], ssq[8];
#pragma unroll
    for (int j = 0; j < 8; j++) { ssum[j] = make_float2(0.f, 0.f); ssq[j] = make_float2(0.f, 0.f); }

    const int tid = blockIdx.x * 256 + t;
    const int rstep = gridDim.x * 128;         // 128 rows per block-iteration
    for (int r0 = (tid >> 2) * 2; r0 < N; r0 += rstep) {
        const int r1 = r0 + 1;
        const bool v1 = (r1 < N);
        float2 acc0[8], acc1[8];
#pragma unroll
        for (int j = 0; j < 8; j++) { acc0[j] = sb1p[j]; acc1[j] = acc0[j]; }

        const float4* a0p = (const float4*)(feat + (size_t)r0 * C_);
        const float4* a1p = (const float4*)(feat + (size_t)r1 * C_);
#pragma unroll 4
        for (int kc = 0; kc < 16; kc++) {
            float4 av0 = __ldg(a0p + kc);
            float4 av1 = v1 ? __ldg(a1p + kc) : make_float4(0.f, 0.f, 0.f, 0.f);
#pragma unroll
            for (int u = 0; u < 4; u++) {
                float2 A0 = f2dup(((const float*)&av0)[u]);
                float2 A1 = f2dup(((const float*)&av1)[u]);
                const float4* wr = (const float4*)(sW + (kc * 4 + u) * WROW_ + g * 20);
#pragma unroll
                for (int j2 = 0; j2 < 4; j2++) {
                    float4 w = wr[j2];
                    float2 wl = make_float2(w.x, w.y);
                    float2 wh = make_float2(w.z, w.w);
                    acc0[2 * j2]     = f2fma(A0, wl, acc0[2 * j2]);
                    acc0[2 * j2 + 1] = f2fma(A0, wh, acc0[2 * j2 + 1]);
                    acc1[2 * j2]     = f2fma(A1, wl, acc1[2 * j2]);
                    acc1[2 * j2 + 1] = f2fma(A1, wh, acc1[2 * j2 + 1]);
                }
            }
        }
        // epilogue: stats + store y
#pragma unroll
        for (int j = 0; j < 8; j++) {
            ssum[j] = f2add(ssum[j], acc0[j]);
            ssq[j]  = f2fma(acc0[j], acc0[j], ssq[j]);
        }
        float4* yo0 = (float4*)(g_y + (size_t)r0 * C_ + g * 16);
#pragma unroll
        for (int j2 = 0; j2 < 4; j2++) {
            float4 o;
            o.x = acc0[2 * j2].x;     o.y = acc0[2 * j2].y;
            o.z = acc0[2 * j2 + 1].x; o.w = acc0[2 * j2 + 1].y;
            yo0[j2] = o;
        }
        if (v1) {
#pragma unroll
            for (int j = 0; j < 8; j++) {
                ssum[j] = f2add(ssum[j], acc1[j]);
                ssq[j]  = f2fma(acc1[j], acc1[j], ssq[j]);
            }
            float4* yo1 = (float4*)(g_y + (size_t)r1 * C_ + g * 16);
#pragma unroll
            for (int j2 = 0; j2 < 4; j2++) {
                float4 o;
                o.x = acc1[2 * j2].x;     o.y = acc1[2 * j2].y;
                o.z = acc1[2 * j2 + 1].x; o.w = acc1[2 * j2 + 1].y;
                yo1[j2] = o;
            }
        }
    }

    warp_reduce_g(ssum, ssq);
    block_stats_flush(t, g, ssum, ssq, sStat, g_stats);
}

// --------------------------------------------------------------------------
// Segment-list construction: histogram -> scan -> scatter -> per-segment sort
// --------------------------------------------------------------------------
__global__ __launch_bounds__(256) void k_hist(const int* __restrict__ inv, int N)
{
    for (int r = blockIdx.x * 256 + threadIdx.x; r < N; r += gridDim.x * 256)
        atomicAdd(&g_cnt[__ldg(inv + r)], 1);
}

__global__ __launch_bounds__(1024) void k_scan()
{
    __shared__ int ssum[1024];
    int t = threadIdx.x;
    const int per = (NSEG_ + 1023) / 1024;   // 98
    int lo = t * per, hi = min(lo + per, NSEG_);
    int loc = 0;
    for (int s = lo; s < hi; s++) loc += g_cnt[s];
    ssum[t] = loc;
    __syncthreads();
    for (int off = 1; off < 1024; off <<= 1) {
        int v = (t >= off) ? ssum[t - off] : 0;
        __syncthreads();
        ssum[t] += v;
        __syncthreads();
    }
    int run = (t == 0) ? 0 : ssum[t - 1];
    for (int s = lo; s < hi; s++) { g_base[s] = run; run += g_cnt[s]; }
}

__global__ __launch_bounds__(256) void k_scatter(const int* __restrict__ inv, int N)
{
    for (int r = blockIdx.x * 256 + threadIdx.x; r < N; r += gridDim.x * 256) {
        int s = __ldg(inv + r);
        int p = atomicAdd(&g_cur[s], 1);
        g_list[g_base[s] + p] = r;
    }
}

__global__ __launch_bounds__(256) void k_sortseg()
{
    int s = blockIdx.x * 256 + threadIdx.x;
    if (s >= NSEG_) return;
    int b = g_base[s], n = g_cnt[s];
    for (int i = 1; i < n; i++) {
        int key = g_list[b + i];
        int j = i - 1;
        while (j >= 0 && g_list[b + j] > key) {
            g_list[b + j + 1] = g_list[b + j];
            j--;
        }
        g_list[b + j + 1] = key;
    }
}

// --------------------------------------------------------------------------
// BN affine: a = gamma*rsqrt(var+1e-3), c = beta - mean*a.  which=0 -> BN1.
// --------------------------------------------------------------------------
__global__ void k_aff(const float* __restrict__ gam, const float* __restrict__ bet,
                      int which, double invN)
{
    int c = threadIdx.x;
    if (c < C_) {
        double m = g_stats[which * 128 + c] * invN;
        double v = g_stats[which * 128 + 64 + c] * invN - m * m;
        double a = (double)__ldg(gam + c) * rsqrt(v + 1e-3);
        g_aff[which * 128 + c] = (float)a;
        g_aff[which * 128 + 64 + c] = (float)((double)__ldg(bet + c) - m * a);
    }
}

// --------------------------------------------------------------------------
// k_seg: grid-stride over segments, one warp per segment; lane = channels
// (l, l+32). Sequential fp32 row-ordered sums (bit-matches deterministic
// reference). Emits q AND accumulates BN2 stats segment-side:
//   sum over rows of pos_w*q      = q * S_p
//   sum over rows of (pos_w*q)^2  = q^2 * S_p2
// fp32 per-thread partials -> block fp64 flush (same scheme as pass1).
// --------------------------------------------------------------------------
__global__ __launch_bounds__(256) void k_seg(
    const float* __restrict__ xyz,
    const float* __restrict__ Wpos, const float* __restrict__ bpos)
{
    __shared__ double sStat[128];
    int t = threadIdx.x;
    if (t < 128) sStat[t] = 0.0;
    __syncthreads();

    int l = t & 31;

    float P0a = __ldg(Wpos + l),        P0b = __ldg(Wpos + 32 + l);
    float P1a = __ldg(Wpos + 64 + l),   P1b = __ldg(Wpos + 96 + l);
    float P2a = __ldg(Wpos + 128 + l),  P2b = __ldg(Wpos + 160 + l);
    float Ba  = __ldg(bpos + l),        Bb  = __ldg(bpos + 32 + l);
    float a1a = g_aff[l],       a1b = g_aff[32 + l];
    float c1a = g_aff[64 + l],  c1b = g_aff[96 + l];

    float st_s0 = 0.f, st_q0 = 0.f, st_s1 = 0.f, st_q1 = 0.f;

    const int w0 = blockIdx.x * 8 + (t >> 5);
    const int wstep = gridDim.x * 8;
    for (int w = w0; w < NSEG_; w += wstep) {
        int b = g_base[w], n = g_cnt[w];
        float sp0 = 0.f, sp1 = 0.f, sy0 = 0.f, sy1 = 0.f;
        float sp2_0 = 0.f, sp2_1 = 0.f;
        for (int i = 0; i < n; i++) {
            int r = g_list[b + i];
            float fx = floorf(__ldg(xyz + 3 * r));
            float fy = floorf(__ldg(xyz + 3 * r + 1));
            float fz = floorf(__ldg(xyz + 3 * r + 2));
            float pwa = __fadd_rn(fmaf(fz, P2a, fmaf(fy, P1a, __fmul_rn(fx, P0a))), Ba);
            float pwb = __fadd_rn(fmaf(fz, P2b, fmaf(fy, P1b, __fmul_rn(fx, P0b))), Bb);
            float ya = __ldg(g_y + (size_t)r * C_ + l);
            float yb = __ldg(g_y + (size_t)r * C_ + 32 + l);
            float fa = fmaf(a1a, ya, c1a);
            float fb = fmaf(a1b, yb, c1b);
            sp0 = __fadd_rn(sp0, pwa);
            sp1 = __fadd_rn(sp1, pwb);
            sy0 = __fadd_rn(sy0, __fmul_rn(pwa, fa));
            sy1 = __fadd_rn(sy1, __fmul_rn(pwb, fb));
            sp2_0 = fmaf(pwa, pwa, sp2_0);
            sp2_1 = fmaf(pwb, pwb, sp2_1);
        }
        float qa = __fdiv_rn(-sy0, __fadd_rn(sp0, 1e-4f));
        float qb = __fdiv_rn(-sy1, __fadd_rn(sp1, 1e-4f));
        g_q[(size_t)w * C_ + l]      = qa;
        g_q[(size_t)w * C_ + 32 + l] = qb;
        st_s0 = fmaf(qa, sp0, st_s0);
        st_s1 = fmaf(qb, sp1, st_s1);
        st_q0 = fmaf(qa * qa, sp2_0, st_q0);
        st_q1 = fmaf(qb * qb, sp2_1, st_q1);
    }

    // block-level fp64 reduction of BN2 stats, then global flush
    atomicAdd(&sStat[l],       (double)st_s0);
    atomicAdd(&sStat[32 + l],  (double)st_s1);
    atomicAdd(&sStat[64 + l],  (double)st_q0);
    atomicAdd(&sStat[96 + l],  (double)st_q1);
    __syncthreads();
    if (t < 128) atomicAdd(&g_stats[128 + t], sStat[t]);
}

// --------------------------------------------------------------------------
// Final: out = relu(a2*(pos_w*q[seg]) + c2) + (a1*y + c1)
// --------------------------------------------------------------------------
__global__ __launch_bounds__(256, 2) void k_final(
    const float* __restrict__ xyz, const int* __restrict__ inv,
    const float* __restrict__ Wpos, const float* __restrict__ bpos,
    float* __restrict__ out, int N)
{
    __shared__ float sP[3 * C_];
    __shared__ float sb2[C_];
    __shared__ float saff[4 * C_];
    int t = threadIdx.x;
    if (t < 48) ((float4*)sP)[t] = ((const float4*)Wpos)[t];
    if (t >= 64 && t < 80) ((float4*)sb2)[t - 64] = ((const float4*)bpos)[t - 64];
    if (t >= 128 && t < 192) ((float4*)saff)[t - 128] = ((const float4*)g_aff)[t - 128];
    __syncthreads();

    const int g = t & 3;
    const float2* P0 = (const float2*)sP + g * 8;
    const float2* P1 = (const float2*)(sP + 64) + g * 8;
    const float2* P2 = (const float2*)(sP + 128) + g * 8;
    const float2* sbp = (const float2*)sb2 + g * 8;
    const float2* A1 = (const float2*)saff + g * 8;
    const float2* C1 = (const float2*)(saff + 64) + g * 8;
    const float2* A2 = (const float2*)(saff + 128) + g * 8;
    const float2* C2 = (const float2*)(saff + 192) + g * 8;

    const int tid = blockIdx.x * 256 + t;
    const int rstep = gridDim.x * 64;
    for (int r = tid >> 2; r < N; r += rstep) {
        float fx = floorf(__ldg(xyz + (size_t)r * 3 + 0));
        float fy = floorf(__ldg(xyz + (size_t)r * 3 + 1));
        float fz = floorf(__ldg(xyz + (size_t)r * 3 + 2));
        float2 X = f2dup(fx), Y = f2dup(fy), Z = f2dup(fz);
        int s = __ldg(inv + r);
        const float4* qr = (const float4*)(g_q + (size_t)s * C_ + g * 16);
        const float4* yr = (const float4*)(g_y + (size_t)r * C_ + g * 16);
        float4* orow = (float4*)(out + (size_t)r * C_ + g * 16);
#pragma unroll
        for (int j2 = 0; j2 < 4; j2++) {
            float4 qv = __ldg(qr + j2);
            float4 yv = yr[j2];
            float2 pl = posw2(X, Y, Z, P0[2 * j2], P1[2 * j2], P2[2 * j2], sbp[2 * j2]);
            float2 ph = posw2(X, Y, Z, P0[2 * j2 + 1], P1[2 * j2 + 1], P2[2 * j2 + 1],
                              sbp[2 * j2 + 1]);
            float2 featl = f2fma(A1[2 * j2],     make_float2(yv.x, yv.y), C1[2 * j2]);
            float2 feath = f2fma(A1[2 * j2 + 1], make_float2(yv.z, yv.w), C1[2 * j2 + 1]);
            float2 opl = f2mul(pl, make_float2(qv.x, qv.y));
            float2 oph = f2mul(ph, make_float2(qv.z, qv.w));
            float2 bnl = f2fma(A2[2 * j2],     opl, C2[2 * j2]);
            float2 bnh = f2fma(A2[2 * j2 + 1], oph, C2[2 * j2 + 1]);
            float4 o;
            o.x = fmaxf(bnl.x, 0.f) + featl.x;
            o.y = fmaxf(bnl.y, 0.f) + featl.y;
            o.z = fmaxf(bnh.x, 0.f) + feath.x;
            o.w = fmaxf(bnh.y, 0.f) + feath.y;
            orow[j2] = o;
        }
    }
}

// --------------------------------------------------------------------------
extern "C" void kernel_launch(void* const* d_in, const int* in_sizes, int n_in,
                              void* d_out, int out_size)
{
    const float* xyz  = (const float*)d_in[0];
    const float* feat = (const float*)d_in[1];
    const int*   inv  = (const int*)d_in[2];
    const float* Wpre = (const float*)d_in[3];
    const float* bpre = (const float*)d_in[4];
    const float* g1   = (const float*)d_in[5];
    const float* be1  = (const float*)d_in[6];
    const float* Wpos = (const float*)d_in[7];
    const float* bpos = (const float*)d_in[8];
    const float* g2   = (const float*)d_in[9];
    const float* be2  = (const float*)d_in[10];
    float* out = (float*)d_out;
    const int N = in_sizes[1] / C_;

    void *pCnt = nullptr, *pCur = nullptr, *pStats = nullptr;
    cudaGetSymbolAddress(&pCnt, g_cnt);
    cudaGetSymbolAddress(&pCur, g_cur);
    cudaGetSymbolAddress(&pStats, g_stats);

    cudaMemsetAsync(pCnt, 0, sizeof(int) * NSEG_, 0);
    cudaMemsetAsync(pCur, 0, sizeof(int) * NSEG_, 0);
    cudaMemsetAsync(pStats, 0, sizeof(double) * 4 * C_, 0);

    const int grid = 1184;
    const double invN = 1.0 / (double)N;

    // order arranged so k_pass1 lands in the ncu capture slot
    k_hist<<<grid, 256>>>(inv, N);
    k_scan<<<1, 1024>>>();
    k_scatter<<<grid, 256>>>(inv, N);
    k_pass1<<<grid, 256>>>(feat, Wpre, bpre, N);
    k_sortseg<<<(NSEG_ + 255) / 256, 256>>>();
    k_aff<<<1, 64>>>(g1, be1, 0, invN);

    // sequential per-segment sums -> q, + BN2 stats (pass2 fused away)
    k_seg<<<grid, 256>>>(xyz, Wpos, bpos);
    k_aff<<<1, 64>>>(g2, be2, 1, invN);
    k_final<<<grid, 256>>>(xyz, inv, Wpos, bpos, out, N);
}